// round 1
// baseline (speedup 1.0000x reference)
#include <cuda_runtime.h>
#include <cuda_bf16.h>

// Problem constants
#define BB 256
#define OO 10
#define RR 1152
#define II 8
#define DD 16
#define NITER 3

#define PAD 17            // priors SMEM row stride (floats); 17 coprime with 32 banks
#define NT  256           // threads per CTA in routing kernel

// Scratch for priors [B, O, R, D] — device global (no allocations allowed).
__device__ float g_priors[(size_t)BB * OO * RR * DD];

// ---------------------------------------------------------------------------
// Kernel 1: priors[b,o,r,d] = sum_i inputs[b,r,i] * W[o,r,i,d]
// Grid: (R/16)*O CTAs, 256 threads. Each thread owns one (r,d), holds its 8
// W values in registers, streams over all 256 batches.
// W is read exactly once chip-wide (5.9 MB); output write is the cost (189 MB).
// ---------------------------------------------------------------------------
__global__ __launch_bounds__(256) void priors_kernel(
    const float* __restrict__ in,   // [B, R, I]
    const float* __restrict__ W,    // [O, R, I, D]
    float* __restrict__ out)        // [B, O, R, D]
{
    const int tid = threadIdx.x;
    const int d  = tid & 15;
    const int rl = tid >> 4;                 // 0..15
    const int o  = blockIdx.x % OO;
    const int rt = blockIdx.x / OO;          // 0..71
    const int r  = rt * 16 + rl;

    // Register-resident W[o, r, 0..7, d]
    float w[8];
    const float* wp = W + ((size_t)(o * RR + r) * II) * DD + d;
    #pragma unroll
    for (int i = 0; i < 8; ++i) w[i] = wp[i * DD];

    const float* ip = in + (size_t)r * II;                 // advances by R*I per b
    float* op = out + ((size_t)(o * RR + r)) * DD + d;     // advances by O*R*D per b

    #pragma unroll 4
    for (int b = 0; b < BB; ++b) {
        float4 a = *reinterpret_cast<const float4*>(ip);
        float4 c = *reinterpret_cast<const float4*>(ip + 4);
        float acc = a.x * w[0] + a.y * w[1] + a.z * w[2] + a.w * w[3]
                  + c.x * w[4] + c.y * w[5] + c.z * w[6] + c.w * w[7];
        *op = acc;
        ip += RR * II;
        op += (size_t)OO * RR * DD;
    }
}

// ---------------------------------------------------------------------------
// Kernel 2: dynamic routing. One CTA per (b,o) pair (2560 CTAs).
// Loads the 72KB priors tile into padded SMEM once, then runs 3 iterations
// entirely in SMEM. Logits are scalar-per-r (constant over D in the math).
// ---------------------------------------------------------------------------
__global__ __launch_bounds__(NT) void route_kernel(
    const float* __restrict__ priG,   // [B, O, R, D]
    float* __restrict__ out)          // [B, O, 1, D]
{
    extern __shared__ float sm[];
    float* pri  = sm;                     // RR * PAD
    float* lg   = pri + RR * PAD;         // RR   (logits)
    float* pb   = lg + RR;                // RR   (exp(logit - max))
    float* part = pb + RR;                // NT   (s partials, [g][d])
    float* svec = part + NT;              // 16
    float* red  = svec + 16;              // 8    (block reduce scratch)

    const int tid  = threadIdx.x;
    const int lane = tid & 31;
    const int wid  = tid >> 5;
    const int d    = tid & 15;
    const int g    = tid >> 4;
    const int pair = blockIdx.x;          // b * O + o

    // Load priors tile into padded SMEM (scalar stores; rows are 68B apart)
    const float4* g4 = reinterpret_cast<const float4*>(priG + (size_t)pair * (RR * DD));
    for (int idx = tid; idx < RR * DD / 4; idx += NT) {
        float4 v = g4[idx];
        int r = idx >> 2;
        int j = (idx & 3) << 2;
        float* dst = pri + r * PAD + j;
        dst[0] = v.x; dst[1] = v.y; dst[2] = v.z; dst[3] = v.w;
    }
    for (int r = tid; r < RR; r += NT) lg[r] = 0.0f;
    __syncthreads();

    for (int it = 0; it < NITER; ++it) {
        // ---- softmax over r: max ----
        float mx = -1e30f;
        for (int r = tid; r < RR; r += NT) mx = fmaxf(mx, lg[r]);
        #pragma unroll
        for (int off = 16; off; off >>= 1)
            mx = fmaxf(mx, __shfl_xor_sync(0xffffffffu, mx, off));
        if (lane == 0) red[wid] = mx;
        __syncthreads();
        if (tid == 0) {
            float m = red[0];
            for (int w2 = 1; w2 < NT / 32; ++w2) m = fmaxf(m, red[w2]);
            red[0] = m;
        }
        __syncthreads();
        mx = red[0];
        __syncthreads();   // all reads of red[0] done before reuse below

        // ---- softmax: exp + sum ----
        float sum = 0.0f;
        for (int r = tid; r < RR; r += NT) {
            float e = __expf(lg[r] - mx);
            pb[r] = e;
            sum += e;
        }
        #pragma unroll
        for (int off = 16; off; off >>= 1)
            sum += __shfl_xor_sync(0xffffffffu, sum, off);
        if (lane == 0) red[wid] = sum;
        __syncthreads();
        if (tid == 0) {
            float s = 0.0f;
            for (int w2 = 0; w2 < NT / 32; ++w2) s += red[w2];
            red[0] = s;
        }
        __syncthreads();
        const float inv = 1.0f / red[0];

        // ---- s[d] = sum_r p[r] * priors[r,d] ----
        float acc = 0.0f;
        for (int k = g; k < RR; k += 16)
            acc += pb[k] * pri[k * PAD + d];
        part[tid] = acc;                       // part[g*16 + d]
        __syncthreads();
        if (tid < 16) {
            float s = 0.0f;
            #pragma unroll
            for (int gg = 0; gg < 16; ++gg) s += part[gg * 16 + tid];
            svec[tid] = s * inv;               // fold 1/sum here
        }
        __syncthreads();

        // ---- squash scale (computed redundantly; 16 loads + 16 FMA) ----
        float sq = 0.0f;
        #pragma unroll
        for (int d2 = 0; d2 < 16; ++d2) { float v = svec[d2]; sq += v * v; }
        float scale = (sq / (1.0f + sq)) * rsqrtf(sq);

        if (it == NITER - 1) {
            if (tid < 16) out[pair * DD + tid] = scale * svec[tid];
        } else {
            // ---- logits[r] += scale * dot(priors[r,:], svec) ----
            for (int r = tid; r < RR; r += NT) {
                float dt = 0.0f;
                #pragma unroll
                for (int d2 = 0; d2 < 16; ++d2) dt += pri[r * PAD + d2] * svec[d2];
                lg[r] += scale * dt;
            }
            __syncthreads();
        }
    }
}

// ---------------------------------------------------------------------------
extern "C" void kernel_launch(void* const* d_in, const int* in_sizes, int n_in,
                              void* d_out, int out_size)
{
    const float* in = (const float*)d_in[0];   // inputs [B,R,I]
    const float* W  = (const float*)d_in[1];   // route_weights [O,R,I,D]
    float* out = (float*)d_out;                // [B,O,1,D] fp32

    float* pri = nullptr;
    cudaGetSymbolAddress((void**)&pri, g_priors);

    // K1: 720 CTAs x 256 threads
    priors_kernel<<<(RR / 16) * OO, 256>>>(in, W, pri);

    // K2: 2560 CTAs x 256 threads, 88.7 KB dynamic SMEM
    const size_t smem = (size_t)(RR * PAD + RR + RR + NT + 16 + 8) * sizeof(float);
    static bool attr_set = false;
    cudaFuncSetAttribute(route_kernel,
                         cudaFuncAttributeMaxDynamicSharedMemorySize, (int)smem);
    (void)attr_set;
    route_kernel<<<BB * OO, NT, smem>>>(pri, out);
}

// round 2
// speedup vs baseline: 2.0448x; 2.0448x over previous
#include <cuda_runtime.h>
#include <cuda_bf16.h>

#define BB 256
#define OO 10
#define RR 1152
#define II 8
#define DD 16
#define NITER 3
#define NT 256

// Scratch for priors [B, O, R, D] — device global (no allocations allowed).
__device__ float g_priors[(size_t)BB * OO * RR * DD];

// ---- packed f32x2 helpers (Blackwell) --------------------------------------
__device__ __forceinline__ unsigned long long pack2(float a, float b) {
    unsigned long long r;
    asm("mov.b64 %0, {%1, %2};" : "=l"(r) : "f"(a), "f"(b));
    return r;
}
__device__ __forceinline__ unsigned long long fma2(unsigned long long a,
                                                   unsigned long long b,
                                                   unsigned long long c) {
    unsigned long long d;
    asm("fma.rn.f32x2 %0, %1, %2, %3;" : "=l"(d) : "l"(a), "l"(b), "l"(c));
    return d;
}
__device__ __forceinline__ unsigned long long mul2(unsigned long long a,
                                                   unsigned long long b) {
    unsigned long long d;
    asm("mul.rn.f32x2 %0, %1, %2;" : "=l"(d) : "l"(a), "l"(b));
    return d;
}
__device__ __forceinline__ void unpack2(unsigned long long v, float& lo, float& hi) {
    asm("mov.b64 {%0, %1}, %2;" : "=f"(lo), "=f"(hi) : "l"(v));
}

// ---------------------------------------------------------------------------
// Kernel 1: priors[b,o,r,d] = sum_i inputs[b,r,i] * W[o,r,i,d]
// Thread owns (o, r, c) with c = 4 consecutive d's; 16 packed-f32x2 W regs;
// streams 64 batches with f32x2 FMAs and one STG.128 per batch.
// Grid: O(10) * RT(18) * BT(4) = 720 CTAs x 256 threads.
// ---------------------------------------------------------------------------
__global__ __launch_bounds__(256) void priors_kernel(
    const float* __restrict__ in,   // [B, R, I]
    const float* __restrict__ W,    // [O, R, I, D]
    float* __restrict__ out)        // [B, O, R, D]
{
    const int tid = threadIdx.x;
    const int c  = tid & 3;          // which group of 4 d's
    const int rl = tid >> 2;         // 0..63
    const int bt = blockIdx.x & 3;
    const int rt = (blockIdx.x >> 2) % 18;
    const int o  = (blockIdx.x >> 2) / 18;
    const int r  = rt * 64 + rl;

    // W[o,r,i,4c..4c+3] for i=0..7 -> 16 packed f32x2
    unsigned long long w2[16];
    const float4* W4 = reinterpret_cast<const float4*>(W);
    const size_t wbase = ((size_t)(o * RR + r) * II) * 4 + c; // float4 index
    #pragma unroll
    for (int i = 0; i < 8; ++i) {
        float4 wv = W4[wbase + (size_t)i * 4];
        w2[2 * i]     = pack2(wv.x, wv.y);
        w2[2 * i + 1] = pack2(wv.z, wv.w);
    }

    const float4* in4 = reinterpret_cast<const float4*>(in)
                      + ((size_t)(bt * 64) * RR + r) * 2;     // (b*R+r)*8 floats
    float4* out4 = reinterpret_cast<float4*>(out)
                 + (((size_t)(bt * 64) * OO + o) * RR + r) * 4 + c;

    #pragma unroll 2
    for (int b = 0; b < 64; ++b) {
        float4 a = in4[0];
        float4 e = in4[1];
        unsigned long long p0 = pack2(a.x, a.x), p1 = pack2(a.y, a.y);
        unsigned long long p2 = pack2(a.z, a.z), p3 = pack2(a.w, a.w);
        unsigned long long p4 = pack2(e.x, e.x), p5 = pack2(e.y, e.y);
        unsigned long long p6 = pack2(e.z, e.z), p7 = pack2(e.w, e.w);

        unsigned long long a01 = mul2(w2[0],  p0);
        unsigned long long a23 = mul2(w2[1],  p0);
        a01 = fma2(w2[2],  p1, a01);  a23 = fma2(w2[3],  p1, a23);
        a01 = fma2(w2[4],  p2, a01);  a23 = fma2(w2[5],  p2, a23);
        a01 = fma2(w2[6],  p3, a01);  a23 = fma2(w2[7],  p3, a23);
        a01 = fma2(w2[8],  p4, a01);  a23 = fma2(w2[9],  p4, a23);
        a01 = fma2(w2[10], p5, a01);  a23 = fma2(w2[11], p5, a23);
        a01 = fma2(w2[12], p6, a01);  a23 = fma2(w2[13], p6, a23);
        a01 = fma2(w2[14], p7, a01);  a23 = fma2(w2[15], p7, a23);

        float4 ov;
        unpack2(a01, ov.x, ov.y);
        unpack2(a23, ov.z, ov.w);
        *out4 = ov;

        in4  += RR * 2;
        out4 += (size_t)OO * RR * 4;
    }
}

// ---------------------------------------------------------------------------
// Kernel 2: dynamic routing. One CTA per (b,o) (2560 CTAs, 256 threads).
// Priors tile (72KB) in row-major SMEM (stride 16 -> all LDS.128 conflict
// free). Logits live in registers (18/thread). Softmax exp+sum fused into the
// weighted-sum pass; running max tracked in the delta pass.
// ---------------------------------------------------------------------------
__global__ __launch_bounds__(NT) void route_kernel(
    const float* __restrict__ priG,   // [B, O, R, D]
    float* __restrict__ out)          // [B, O, 1, D]
{
    extern __shared__ float sm[];
    float4* pri4  = reinterpret_cast<float4*>(sm);   // RR*DD floats = 4608 float4
    float* waccF  = sm + RR * DD;                    // 8 warps * 4 c * 4 = 128
    float* wesF   = waccF + 128;                     // 32
    float* svec   = wesF + 32;                       // 16
    float* sred   = svec + 16;                       // 8
    float* pscale = sred + 8;                        // 1

    const int tid  = threadIdx.x;
    const int lane = tid & 31;
    const int wid  = tid >> 5;
    const int c    = tid & 3;        // d-chunk 0..3
    const int g    = tid >> 2;       // 0..63 (k/r group)
    const int pair = blockIdx.x;     // b * O + o

    // Load priors tile (layout identical: row-major, stride 16 floats)
    const float4* gp = reinterpret_cast<const float4*>(priG)
                     + (size_t)pair * (RR * DD / 4);
    #pragma unroll
    for (int j = 0; j < 18; ++j)
        pri4[j * 256 + tid] = gp[j * 256 + tid];
    __syncthreads();

    float lgr[18];            // logits for rows k = j*64+g (replicated over c)
    float mx = 0.0f;
    float scale = 0.0f;
    float4 sv4;

    #pragma unroll
    for (int it = 0; it < NITER; ++it) {
        // ---- fused exp + sum + weighted sum:  acc = sum_k e_k * pri[k, 4c..] ----
        float4 acc = make_float4(0.f, 0.f, 0.f, 0.f);
        float es = 0.0f;
        #pragma unroll
        for (int j = 0; j < 18; ++j) {
            float e = (it == 0) ? 1.0f : __expf(lgr[j] - mx);
            float4 v = pri4[(j * 64 + g) * 4 + c];
            acc.x += e * v.x; acc.y += e * v.y;
            acc.z += e * v.z; acc.w += e * v.w;
            es += e;
        }
        #pragma unroll
        for (int off = 4; off <= 16; off <<= 1) {
            acc.x += __shfl_xor_sync(0xffffffffu, acc.x, off);
            acc.y += __shfl_xor_sync(0xffffffffu, acc.y, off);
            acc.z += __shfl_xor_sync(0xffffffffu, acc.z, off);
            acc.w += __shfl_xor_sync(0xffffffffu, acc.w, off);
            es    += __shfl_xor_sync(0xffffffffu, es, off);
        }
        if (lane < 4) {                       // lanes 0..3 hold c = 0..3 sums
            int i4 = wid * 4 + lane;
            reinterpret_cast<float4*>(waccF)[i4] = acc;
            wesF[i4] = es;
        }
        __syncthreads();

        // ---- finalize svec (16 threads) + squash scale ----
        if (tid < 16) {
            const int c2 = tid >> 2, e2 = tid & 3;
            float s = 0.0f, et = 0.0f;
            #pragma unroll
            for (int w = 0; w < 8; ++w) {
                s  += waccF[(w * 4 + c2) * 4 + e2];
                et += wesF[w * 4 + c2];
            }
            float sv = s / et;
            svec[tid] = sv;
            float sq = sv * sv;
            #pragma unroll
            for (int off = 1; off < 16; off <<= 1)
                sq += __shfl_xor_sync(0x0000ffffu, sq, off);
            if (tid == 0)
                pscale[0] = (sq / (1.0f + sq)) * rsqrtf(sq);
        }
        __syncthreads();
        scale = pscale[0];
        sv4 = reinterpret_cast<float4*>(svec)[c];

        if (it == NITER - 1) break;

        // ---- delta pass: lgr[j] += scale * dot(pri[r,:], svec); track max ----
        float lmax = -1e30f;
        #pragma unroll
        for (int j = 0; j < 18; ++j) {
            float4 v = pri4[(j * 64 + g) * 4 + c];
            float dt = v.x * sv4.x + v.y * sv4.y + v.z * sv4.z + v.w * sv4.w;
            dt += __shfl_xor_sync(0xffffffffu, dt, 1);
            dt += __shfl_xor_sync(0xffffffffu, dt, 2);
            float nl = ((it == 0) ? 0.0f : lgr[j]) + scale * dt;
            lgr[j] = nl;
            lmax = fmaxf(lmax, nl);
        }
        #pragma unroll
        for (int off = 16; off; off >>= 1)
            lmax = fmaxf(lmax, __shfl_xor_sync(0xffffffffu, lmax, off));
        if (lane == 0) sred[wid] = lmax;
        __syncthreads();
        mx = sred[0];
        #pragma unroll
        for (int w = 1; w < 8; ++w) mx = fmaxf(mx, sred[w]);
    }

    if (tid < 16)
        out[pair * DD + tid] = scale * svec[tid];
}

// ---------------------------------------------------------------------------
extern "C" void kernel_launch(void* const* d_in, const int* in_sizes, int n_in,
                              void* d_out, int out_size)
{
    const float* in = (const float*)d_in[0];   // inputs [B,R,I]
    const float* W  = (const float*)d_in[1];   // route_weights [O,R,I,D]
    float* out = (float*)d_out;                // [B,O,1,D] fp32

    float* pri = nullptr;
    cudaGetSymbolAddress((void**)&pri, g_priors);

    // K1: 720 CTAs x 256 threads
    priors_kernel<<<OO * 18 * 4, 256>>>(in, W, pri);

    // K2: 2560 CTAs x 256 threads, ~73 KB dynamic SMEM (3 CTAs/SM)
    const size_t smem = (size_t)(RR * DD + 256) * sizeof(float);
    cudaFuncSetAttribute(route_kernel,
                         cudaFuncAttributeMaxDynamicSharedMemorySize, (int)smem);
    route_kernel<<<BB * OO, NT, smem>>>(pri, out);
}

// round 3
// speedup vs baseline: 2.8788x; 1.4079x over previous
#include <cuda_runtime.h>
#include <cuda_fp16.h>
#include <cuda_bf16.h>

#define BB 256
#define OO 10
#define RR 1152
#define II 8
#define DD 16
#define NITER 3
#define NT 256

// Scratch for priors [B, O, R, D] in fp16 — device global (no allocations).
__device__ __half2 g_priors[(size_t)BB * OO * RR * DD / 2];

// ---- packed f32x2 helpers (Blackwell) --------------------------------------
__device__ __forceinline__ unsigned long long pack2(float a, float b) {
    unsigned long long r;
    asm("mov.b64 %0, {%1, %2};" : "=l"(r) : "f"(a), "f"(b));
    return r;
}
__device__ __forceinline__ unsigned long long fma2(unsigned long long a,
                                                   unsigned long long b,
                                                   unsigned long long c) {
    unsigned long long d;
    asm("fma.rn.f32x2 %0, %1, %2, %3;" : "=l"(d) : "l"(a), "l"(b), "l"(c));
    return d;
}
__device__ __forceinline__ unsigned long long mul2(unsigned long long a,
                                                   unsigned long long b) {
    unsigned long long d;
    asm("mul.rn.f32x2 %0, %1, %2;" : "=l"(d) : "l"(a), "l"(b));
    return d;
}
__device__ __forceinline__ void unpack2(unsigned long long v, float& lo, float& hi) {
    asm("mov.b64 {%0, %1}, %2;" : "=f"(lo), "=f"(hi) : "l"(v));
}

// ---------------------------------------------------------------------------
// Kernel 1: priors[b,o,r,d] = sum_i inputs[b,r,i] * W[o,r,i,d], stored fp16.
// Thread owns (o, r, c=4 d's); 16 packed-f32x2 W regs; streams 64 batches.
// ---------------------------------------------------------------------------
__global__ __launch_bounds__(256) void priors_kernel(
    const float* __restrict__ in,   // [B, R, I]
    const float* __restrict__ W,    // [O, R, I, D]
    uint2* __restrict__ out)        // [B, O, R, D] as fp16 (uint2 = 4 halfs)
{
    const int tid = threadIdx.x;
    const int c  = tid & 3;
    const int rl = tid >> 2;                 // 0..63
    const int bt = blockIdx.x & 3;
    const int rt = (blockIdx.x >> 2) % 18;
    const int o  = (blockIdx.x >> 2) / 18;
    const int r  = rt * 64 + rl;

    unsigned long long w2[16];
    const float4* W4 = reinterpret_cast<const float4*>(W);
    const size_t wbase = ((size_t)(o * RR + r) * II) * 4 + c;
    #pragma unroll
    for (int i = 0; i < 8; ++i) {
        float4 wv = W4[wbase + (size_t)i * 4];
        w2[2 * i]     = pack2(wv.x, wv.y);
        w2[2 * i + 1] = pack2(wv.z, wv.w);
    }

    const float4* in4 = reinterpret_cast<const float4*>(in)
                      + ((size_t)(bt * 64) * RR + r) * 2;
    uint2* outp = out + (((size_t)(bt * 64) * OO + o) * RR + r) * 4 + c;

    #pragma unroll 2
    for (int b = 0; b < 64; ++b) {
        float4 a = in4[0];
        float4 e = in4[1];
        unsigned long long p0 = pack2(a.x, a.x), p1 = pack2(a.y, a.y);
        unsigned long long p2 = pack2(a.z, a.z), p3 = pack2(a.w, a.w);
        unsigned long long p4 = pack2(e.x, e.x), p5 = pack2(e.y, e.y);
        unsigned long long p6 = pack2(e.z, e.z), p7 = pack2(e.w, e.w);

        unsigned long long a01 = mul2(w2[0],  p0);
        unsigned long long a23 = mul2(w2[1],  p0);
        a01 = fma2(w2[2],  p1, a01);  a23 = fma2(w2[3],  p1, a23);
        a01 = fma2(w2[4],  p2, a01);  a23 = fma2(w2[5],  p2, a23);
        a01 = fma2(w2[6],  p3, a01);  a23 = fma2(w2[7],  p3, a23);
        a01 = fma2(w2[8],  p4, a01);  a23 = fma2(w2[9],  p4, a23);
        a01 = fma2(w2[10], p5, a01);  a23 = fma2(w2[11], p5, a23);
        a01 = fma2(w2[12], p6, a01);  a23 = fma2(w2[13], p6, a23);
        a01 = fma2(w2[14], p7, a01);  a23 = fma2(w2[15], p7, a23);

        float4 ov;
        unpack2(a01, ov.x, ov.y);
        unpack2(a23, ov.z, ov.w);
        __half2 h0 = __floats2half2_rn(ov.x, ov.y);
        __half2 h1 = __floats2half2_rn(ov.z, ov.w);
        uint2 st;
        st.x = *reinterpret_cast<unsigned*>(&h0);
        st.y = *reinterpret_cast<unsigned*>(&h1);
        *outp = st;

        in4  += RR * 2;
        outp += (size_t)OO * RR * 4;
    }
}

// ---------------------------------------------------------------------------
// Kernel 2: dynamic routing. One CTA per (b,o) (2560 CTAs, 256 threads).
// fp16 priors tile (36.9 KB) in SMEM -> 6 CTAs/SM. Logits in registers.
// No softmax max-subtraction (logits bounded ~|25|, exp safe in fp32), which
// lets the delta pass fuse with the exp/weighted-sum pass: tile read 3x total.
// ---------------------------------------------------------------------------
__global__ __launch_bounds__(NT) void route_kernel(
    const uint4* __restrict__ priG,   // [B, O, R, D] fp16
    float* __restrict__ out)          // [B, O, 1, D] fp32
{
    extern __shared__ float sm[];
    uint2* priH   = reinterpret_cast<uint2*>(sm);    // RR*4 uint2 = 36864 B
    float* waccF  = sm + RR * DD / 2;                // 8 warps * 4 c * 4 = 128
    float* wesF   = waccF + 128;                     // 32
    float* svec   = wesF + 32;                       // 16
    float* pscale = svec + 16;                       // 1

    const int tid  = threadIdx.x;
    const int lane = tid & 31;
    const int wid  = tid >> 5;
    const int c    = tid & 3;        // d-chunk 0..3
    const int g    = tid >> 2;       // 0..63 (row group)
    const int pair = blockIdx.x;     // b * O + o

    // Load fp16 priors tile: 2304 uint4
    {
        const uint4* gp = priG + (size_t)pair * (RR * DD / 8);
        uint4* sp = reinterpret_cast<uint4*>(priH);
        #pragma unroll
        for (int j = 0; j < 9; ++j)
            sp[j * 256 + tid] = gp[j * 256 + tid];
    }
    __syncthreads();

    float lgr[18];
    #pragma unroll
    for (int j = 0; j < 18; ++j) lgr[j] = 0.0f;
    float scale = 0.0f;
    float4 sv4 = make_float4(0.f, 0.f, 0.f, 0.f);

    #pragma unroll
    for (int it = 0; it < NITER; ++it) {
        // ---- fused pass: (logit update w/ prev svec) + exp + weighted sum ----
        float4 acc = make_float4(0.f, 0.f, 0.f, 0.f);
        float es = 0.0f;
        #pragma unroll
        for (int j = 0; j < 18; ++j) {
            uint2 hv = priH[(j * 64 + g) * 4 + c];
            float2 f0 = __half22float2(*reinterpret_cast<__half2*>(&hv.x));
            float2 f1 = __half22float2(*reinterpret_cast<__half2*>(&hv.y));
            float e;
            if (it == 0) {
                e = 1.0f;
            } else {
                float dt = f0.x * sv4.x + f0.y * sv4.y
                         + f1.x * sv4.z + f1.y * sv4.w;
                dt += __shfl_xor_sync(0xffffffffu, dt, 1);
                dt += __shfl_xor_sync(0xffffffffu, dt, 2);
                lgr[j] += scale * dt;
                e = __expf(lgr[j]);
            }
            acc.x += e * f0.x; acc.y += e * f0.y;
            acc.z += e * f1.x; acc.w += e * f1.y;
            es += e;
        }
        #pragma unroll
        for (int off = 4; off <= 16; off <<= 1) {
            acc.x += __shfl_xor_sync(0xffffffffu, acc.x, off);
            acc.y += __shfl_xor_sync(0xffffffffu, acc.y, off);
            acc.z += __shfl_xor_sync(0xffffffffu, acc.z, off);
            acc.w += __shfl_xor_sync(0xffffffffu, acc.w, off);
            es    += __shfl_xor_sync(0xffffffffu, es, off);
        }
        if (lane < 4) {
            int i4 = wid * 4 + lane;
            reinterpret_cast<float4*>(waccF)[i4] = acc;
            wesF[i4] = es;
        }
        __syncthreads();

        // ---- finalize svec (16 threads) + squash scale ----
        if (tid < 16) {
            const int c2 = tid >> 2, e2 = tid & 3;
            float s = 0.0f, et = 0.0f;
            #pragma unroll
            for (int w = 0; w < 8; ++w) {
                s  += waccF[(w * 4 + c2) * 4 + e2];
                et += wesF[w * 4 + c2];
            }
            float sv = s / et;
            svec[tid] = sv;
            float sq = sv * sv;
            #pragma unroll
            for (int off = 1; off < 16; off <<= 1)
                sq += __shfl_xor_sync(0x0000ffffu, sq, off);
            if (tid == 0)
                pscale[0] = (sq / (1.0f + sq)) * rsqrtf(sq);
        }
        __syncthreads();
        scale = pscale[0];
        sv4 = reinterpret_cast<float4*>(svec)[c];
    }

    if (tid < 16)
        out[pair * DD + tid] = scale * svec[tid];
}

// ---------------------------------------------------------------------------
extern "C" void kernel_launch(void* const* d_in, const int* in_sizes, int n_in,
                              void* d_out, int out_size)
{
    const float* in = (const float*)d_in[0];   // inputs [B,R,I]
    const float* W  = (const float*)d_in[1];   // route_weights [O,R,I,D]
    float* out = (float*)d_out;                // [B,O,1,D] fp32

    void* pri = nullptr;
    cudaGetSymbolAddress(&pri, g_priors);

    // K1: 720 CTAs x 256 threads
    priors_kernel<<<OO * 18 * 4, 256>>>(in, W, (uint2*)pri);

    // K2: 2560 CTAs x 256 threads, ~37.6 KB dynamic SMEM (6 CTAs/SM)
    const size_t smem = (size_t)(RR * DD / 2 + 128 + 32 + 16 + 8) * sizeof(float);
    cudaFuncSetAttribute(route_kernel,
                         cudaFuncAttributeMaxDynamicSharedMemorySize, (int)smem);
    route_kernel<<<BB * OO, NT, smem>>>((const uint4*)pri, out);
}

// round 4
// speedup vs baseline: 3.3895x; 1.1774x over previous
#include <cuda_runtime.h>
#include <cuda_fp16.h>
#include <cuda_bf16.h>

#define BB 256
#define OO 10
#define RR 1152
#define II 8
#define DD 16
#define NITER 3
#define NT 256

// Scratch for priors [B, O, R, D] in fp16 — device global (no allocations).
__device__ __half2 g_priors[(size_t)BB * OO * RR * DD / 2];

// ---- packed f32x2 helpers (Blackwell) --------------------------------------
__device__ __forceinline__ unsigned long long pack2(float a, float b) {
    unsigned long long r;
    asm("mov.b64 %0, {%1, %2};" : "=l"(r) : "f"(a), "f"(b));
    return r;
}
__device__ __forceinline__ unsigned long long fma2(unsigned long long a,
                                                   unsigned long long b,
                                                   unsigned long long c) {
    unsigned long long d;
    asm("fma.rn.f32x2 %0, %1, %2, %3;" : "=l"(d) : "l"(a), "l"(b), "l"(c));
    return d;
}
__device__ __forceinline__ unsigned long long mul2(unsigned long long a,
                                                   unsigned long long b) {
    unsigned long long d;
    asm("mul.rn.f32x2 %0, %1, %2;" : "=l"(d) : "l"(a), "l"(b));
    return d;
}
__device__ __forceinline__ void unpack2(unsigned long long v, float& lo, float& hi) {
    asm("mov.b64 {%0, %1}, %2;" : "=f"(lo), "=f"(hi) : "l"(v));
}

// ---------------------------------------------------------------------------
// Kernel 1: priors[b,o,r,d] = sum_i inputs[b,r,i] * W[o,r,i,d], stored fp16.
// i-paired f32x2: input pairs come FREE from 128-bit loads (no lane-dup MOVs).
// Thread owns (o, r, c=4 d's); 16 W-pair regs; streams 16 batches.
// Grid: O(10) * RT(18) * BT(16) = 2880 CTAs x 256 threads.
// ---------------------------------------------------------------------------
__global__ __launch_bounds__(256) void priors_kernel(
    const float* __restrict__ in,   // [B, R, I]
    const float* __restrict__ W,    // [O, R, I, D]
    uint2* __restrict__ out)        // [B, O, R, D] as fp16 (uint2 = 4 halfs)
{
    const int tid = threadIdx.x;
    const int c  = tid & 3;
    const int rl = tid >> 2;                  // 0..63
    const int bt = blockIdx.x & 15;           // 16 b-tiles of 16
    const int rt = (blockIdx.x >> 4) % 18;
    const int o  = (blockIdx.x >> 4) / 18;
    const int r  = rt * 64 + rl;

    // Load W[o,r,i,4c..4c+3], i=0..7, and pair over i:
    // w2[ip][dl] = ( W[2ip][4c+dl], W[2ip+1][4c+dl] )
    const float4* W4 = reinterpret_cast<const float4*>(W);
    const size_t wbase = ((size_t)(o * RR + r) * II) * 4 + c;
    float4 wv[8];
    #pragma unroll
    for (int i = 0; i < 8; ++i) wv[i] = W4[wbase + (size_t)i * 4];

    unsigned long long w2[4][4];
    #pragma unroll
    for (int ip = 0; ip < 4; ++ip) {
        const float* f0 = reinterpret_cast<const float*>(&wv[2 * ip]);
        const float* f1 = reinterpret_cast<const float*>(&wv[2 * ip + 1]);
        #pragma unroll
        for (int dl = 0; dl < 4; ++dl)
            w2[ip][dl] = pack2(f0[dl], f1[dl]);
    }

    // Input row as packed pairs: 8 floats = 2 x ulonglong2 (pairs are free).
    const ulonglong2* inp = reinterpret_cast<const ulonglong2*>(in)
                          + ((size_t)(bt * 16) * RR + r) * 2;
    uint2* outp = out + (((size_t)(bt * 16) * OO + o) * RR + r) * 4 + c;

    #pragma unroll 4
    for (int b = 0; b < 16; ++b) {
        ulonglong2 q0 = inp[0];   // (in0,in1),(in2,in3)
        ulonglong2 q1 = inp[1];   // (in4,in5),(in6,in7)

        unsigned long long t0 = mul2(w2[0][0], q0.x);
        unsigned long long t1 = mul2(w2[0][1], q0.x);
        unsigned long long t2 = mul2(w2[0][2], q0.x);
        unsigned long long t3 = mul2(w2[0][3], q0.x);
        t0 = fma2(w2[1][0], q0.y, t0);  t1 = fma2(w2[1][1], q0.y, t1);
        t2 = fma2(w2[1][2], q0.y, t2);  t3 = fma2(w2[1][3], q0.y, t3);
        t0 = fma2(w2[2][0], q1.x, t0);  t1 = fma2(w2[2][1], q1.x, t1);
        t2 = fma2(w2[2][2], q1.x, t2);  t3 = fma2(w2[2][3], q1.x, t3);
        t0 = fma2(w2[3][0], q1.y, t0);  t1 = fma2(w2[3][1], q1.y, t1);
        t2 = fma2(w2[3][2], q1.y, t2);  t3 = fma2(w2[3][3], q1.y, t3);

        float l, h;
        unpack2(t0, l, h); float a0 = l + h;
        unpack2(t1, l, h); float a1 = l + h;
        unpack2(t2, l, h); float a2 = l + h;
        unpack2(t3, l, h); float a3 = l + h;

        __half2 h01 = __floats2half2_rn(a0, a1);
        __half2 h23 = __floats2half2_rn(a2, a3);
        uint2 st;
        st.x = *reinterpret_cast<unsigned*>(&h01);
        st.y = *reinterpret_cast<unsigned*>(&h23);
        *outp = st;

        inp  += RR * 2;
        outp += (size_t)OO * RR * 4;
    }
}

// ---------------------------------------------------------------------------
// Kernel 2: dynamic routing. One CTA per (b,o) (2560 CTAs, 256 threads).
// fp16 priors tile (36.9 KB) in SMEM -> 6 CTAs/SM. Logits in registers.
// No softmax max-subtraction (logits bounded, exp safe in fp32); delta pass
// fused with exp/weighted-sum pass: tile read 3x total.
// Pair mapping reversed so first CTAs read most-recently-written (L2-hot) tiles.
// ---------------------------------------------------------------------------
__global__ __launch_bounds__(NT) void route_kernel(
    const uint4* __restrict__ priG,   // [B, O, R, D] fp16
    float* __restrict__ out)          // [B, O, 1, D] fp32
{
    extern __shared__ float sm[];
    uint2* priH   = reinterpret_cast<uint2*>(sm);    // RR*4 uint2 = 36864 B
    float* waccF  = sm + RR * DD / 2;                // 8 warps * 4 c * 4 = 128
    float* wesF   = waccF + 128;                     // 32
    float* svec   = wesF + 32;                       // 16
    float* pscale = svec + 16;                       // 1

    const int tid  = threadIdx.x;
    const int lane = tid & 31;
    const int wid  = tid >> 5;
    const int c    = tid & 3;        // d-chunk 0..3
    const int g    = tid >> 2;       // 0..63 (row group)
    const int pair = (BB * OO - 1) - blockIdx.x;   // reversed for L2 residency

    // Load fp16 priors tile: 2304 uint4
    {
        const uint4* gp = priG + (size_t)pair * (RR * DD / 8);
        uint4* sp = reinterpret_cast<uint4*>(priH);
        #pragma unroll
        for (int j = 0; j < 9; ++j)
            sp[j * 256 + tid] = gp[j * 256 + tid];
    }
    __syncthreads();

    float lgr[18];
    #pragma unroll
    for (int j = 0; j < 18; ++j) lgr[j] = 0.0f;
    float scale = 0.0f;
    float4 sv4 = make_float4(0.f, 0.f, 0.f, 0.f);

    #pragma unroll
    for (int it = 0; it < NITER; ++it) {
        // ---- fused pass: (logit update w/ prev svec) + exp + weighted sum ----
        float4 acc = make_float4(0.f, 0.f, 0.f, 0.f);
        float es = 0.0f;
        #pragma unroll
        for (int j = 0; j < 18; ++j) {
            uint2 hv = priH[(j * 64 + g) * 4 + c];
            float2 f0 = __half22float2(*reinterpret_cast<__half2*>(&hv.x));
            float2 f1 = __half22float2(*reinterpret_cast<__half2*>(&hv.y));
            float e;
            if (it == 0) {
                e = 1.0f;
            } else {
                float dt = f0.x * sv4.x + f0.y * sv4.y
                         + f1.x * sv4.z + f1.y * sv4.w;
                dt += __shfl_xor_sync(0xffffffffu, dt, 1);
                dt += __shfl_xor_sync(0xffffffffu, dt, 2);
                lgr[j] += scale * dt;
                e = __expf(lgr[j]);
            }
            acc.x += e * f0.x; acc.y += e * f0.y;
            acc.z += e * f1.x; acc.w += e * f1.y;
            es += e;
        }
        #pragma unroll
        for (int off = 4; off <= 16; off <<= 1) {
            acc.x += __shfl_xor_sync(0xffffffffu, acc.x, off);
            acc.y += __shfl_xor_sync(0xffffffffu, acc.y, off);
            acc.z += __shfl_xor_sync(0xffffffffu, acc.z, off);
            acc.w += __shfl_xor_sync(0xffffffffu, acc.w, off);
            es    += __shfl_xor_sync(0xffffffffu, es, off);
        }
        if (lane < 4) {
            int i4 = wid * 4 + lane;
            reinterpret_cast<float4*>(waccF)[i4] = acc;
            wesF[i4] = es;
        }
        __syncthreads();

        // ---- finalize svec (16 threads) + squash scale ----
        if (tid < 16) {
            const int c2 = tid >> 2, e2 = tid & 3;
            float s = 0.0f, et = 0.0f;
            #pragma unroll
            for (int w = 0; w < 8; ++w) {
                s  += waccF[(w * 4 + c2) * 4 + e2];
                et += wesF[w * 4 + c2];
            }
            float sv = s / et;
            svec[tid] = sv;
            float sq = sv * sv;
            #pragma unroll
            for (int off = 1; off < 16; off <<= 1)
                sq += __shfl_xor_sync(0x0000ffffu, sq, off);
            if (tid == 0)
                pscale[0] = (sq / (1.0f + sq)) * rsqrtf(sq);
        }
        __syncthreads();
        scale = pscale[0];
        sv4 = reinterpret_cast<float4*>(svec)[c];
    }

    if (tid < 16)
        out[pair * DD + tid] = scale * svec[tid];
}

// ---------------------------------------------------------------------------
extern "C" void kernel_launch(void* const* d_in, const int* in_sizes, int n_in,
                              void* d_out, int out_size)
{
    const float* in = (const float*)d_in[0];   // inputs [B,R,I]
    const float* W  = (const float*)d_in[1];   // route_weights [O,R,I,D]
    float* out = (float*)d_out;                // [B,O,1,D] fp32

    void* pri = nullptr;
    cudaGetSymbolAddress(&pri, g_priors);

    // K1: 2880 CTAs x 256 threads
    priors_kernel<<<OO * 18 * 16, 256>>>(in, W, (uint2*)pri);

    // K2: 2560 CTAs x 256 threads, ~37.6 KB dynamic SMEM (6 CTAs/SM)
    const size_t smem = (size_t)(RR * DD / 2 + 128 + 32 + 16 + 8) * sizeof(float);
    cudaFuncSetAttribute(route_kernel,
                         cudaFuncAttributeMaxDynamicSharedMemorySize, (int)smem);
    route_kernel<<<BB * OO, NT, smem>>>((const uint4*)pri, out);
}